// round 8
// baseline (speedup 1.0000x reference)
#include <cuda_runtime.h>
#include <cstdint>
#include <cstddef>

// Problem constants
static constexpr int B = 8192;
static constexpr int S = 256;
static constexpr int R = 8192;

// 8 MB scratch: inc pre-converted to tf32 bit patterns (device global = sanctioned scratch)
__device__ uint32_t g_incT[(size_t)S * (size_t)R];

// =====================================================================
// Helpers (sm_80-baseline PTX only)
// =====================================================================
__device__ __forceinline__ uint32_t smem_u32(const void* p) {
    uint32_t a;
    asm("{ .reg .u64 t; cvta.to.shared.u64 t, %1; cvt.u32.u64 %0, t; }"
        : "=r"(a) : "l"(p));
    return a;
}
__device__ __forceinline__ void cp_async16(uint32_t s, const void* g) {
    asm volatile("cp.async.cg.shared.global [%0], [%1], 16;"
                 :: "r"(s), "l"(g) : "memory");
}
__device__ __forceinline__ void cp_commit() {
    asm volatile("cp.async.commit_group;" ::: "memory");
}
__device__ __forceinline__ void cp_wait1() {
    asm volatile("cp.async.wait_group 1;" ::: "memory");
}
// SW128 swizzle: XOR byte-addr bits [6:4] with bits [9:7]
__device__ __forceinline__ uint32_t swz128(uint32_t off) {
    return off ^ ((off >> 3) & 0x70);
}
__device__ __forceinline__ uint32_t f2tf32(float f) {
    uint32_t t;
    asm("cvt.rna.tf32.f32 %0, %1;" : "=r"(t) : "f"(f));
    return t;
}
__device__ __forceinline__ void ldsm_x4(uint32_t* r, uint32_t addr) {
    asm volatile("ldmatrix.sync.aligned.m8n8.x4.shared.b16 {%0,%1,%2,%3}, [%4];"
                 : "=r"(r[0]), "=r"(r[1]), "=r"(r[2]), "=r"(r[3]) : "r"(addr));
}
__device__ __forceinline__ void sts128(uint32_t addr, uint32_t v0, uint32_t v1,
                                       uint32_t v2, uint32_t v3) {
    asm volatile("st.shared.v4.b32 [%0], {%1,%2,%3,%4};"
                 :: "r"(addr), "r"(v0), "r"(v1), "r"(v2), "r"(v3) : "memory");
}
__device__ __forceinline__ void mma_m16n8k8(float* c, const uint32_t* a,
                                            const uint32_t* b) {
    asm volatile(
        "mma.sync.aligned.m16n8k8.row.col.f32.tf32.tf32.f32 "
        "{%0,%1,%2,%3}, {%4,%5,%6,%7}, {%8,%9}, {%0,%1,%2,%3};"
        : "+f"(c[0]), "+f"(c[1]), "+f"(c[2]), "+f"(c[3])
        : "r"(a[0]), "r"(a[1]), "r"(a[2]), "r"(a[3]),
          "r"(b[0]), "r"(b[1]));
}

// =====================================================================
// inc -> tf32-bits pre-convert (one-shot, ~5us)
// =====================================================================
__global__ void __launch_bounds__(256) conv_inc_kernel(const float* __restrict__ inc) {
    size_t i = ((size_t)blockIdx.x * 256 + threadIdx.x) * 4;
    float4 v = *reinterpret_cast<const float4*>(inc + i);
    uint4 o;
    o.x = f2tf32(v.x); o.y = f2tf32(v.y); o.z = f2tf32(v.z); o.w = f2tf32(v.w);
    *reinterpret_cast<uint4*>(g_incT + i) = o;
}

// =====================================================================
// Fused flux + GEMM, warp-specialized:
//   warps 0-3 (consumers): pure ldmatrix + mma.sync, warp tile 64x64
//   warps 4-7 (producers): flux compute + cp.async B/P + wait_group
// CTA tile M=64 x N=256 x TK=32. One __syncthreads per K-chunk.
// Groups (committed in iter k): G(k+2) = {B(k+2), P(k+3)}.
// wait_group 1 in iter k  =>  B(k+1), P(k+2) arrived before the barrier.
// Rings: A x2, B x3, P x4 (all hazards distinct).
// =====================================================================
static constexpr int TM = 64, TN = 256, TK = 32;
static constexpr int NK = R / TK;  // 256

static constexpr int A_STAGE = TM * TK * 4;          // 8192
static constexpr int B_STAGE = TN * TK * 4;          // 32768
static constexpr int P_STAGE = 768;
static constexpr int OFF_A = 0;
static constexpr int OFF_B = OFF_A + 2 * A_STAGE;    // 16384
static constexpr int OFF_P = OFF_B + 3 * B_STAGE;    // 114688
static constexpr int OFF_AB = OFF_P + 4 * P_STAGE;   // 117760
static constexpr int AB_PITCH = S + 1;               // 257 (odd: conflict-free gather)
static constexpr int SMEM_USED = OFF_AB + TM * AB_PITCH * 4;  // 183552
static constexpr int SMEM_TOTAL = SMEM_USED + 1024;  // alignment slack

__global__ void __launch_bounds__(256, 1) fused_kernel(
    const float* __restrict__ ab, const float* __restrict__ temp,
    const float* __restrict__ cr, const float* __restrict__ fuv,
    const float* __restrict__ alpha, const float* __restrict__ beta,
    const float* __restrict__ gamma, const int* __restrict__ rm2,
    const int* __restrict__ rtype, float* __restrict__ out)
{
    extern __shared__ char smem_raw[];
    const uint32_t sb_raw = smem_u32(smem_raw);
    const uint32_t sb = (sb_raw + 1023u) & ~1023u;   // SW128-safe tile bases
    char* smem = smem_raw + (sb - sb_raw);

    const int tid = threadIdx.x;
    const int wid = tid >> 5;
    const int lane = tid & 31;
    const int m0 = blockIdx.x * TM;
    const bool is_prod = (wid >= 4);
    const int pw = wid - 4;            // producer warp 0..3
    const int warp_n = wid;            // consumer warp 0..3 -> n block

    float* s_ab = reinterpret_cast<float*>(smem + OFF_AB);

    // ---------------- Prologue: abundances (all 256 threads) ----------------
    for (int i = tid; i < TM * S; i += 256) {
        int bi = i >> 8, si = i & 255;
        s_ab[bi * AB_PITCH + si] = ab[(size_t)(m0 + bi) * S + si];
    }
    if (tid < TM) s_ab[tid * AB_PITCH + S] = 1.0f;  // ones column (index == S)

    // Producer per-lane aux in REGISTERS (b1 = lane, b2 = lane+32)
    float L1 = 0, L2 = 0, iT1 = 0, iT2 = 0, cr1 = 0, cr2 = 0, fv1 = 0, fv2 = 0;
    if (is_prod) {
        const float T1 = temp[m0 + lane], T2 = temp[m0 + lane + 32];
        L1 = __logf(T1 * (1.0f / 300.0f)); iT1 = 1.0f / T1;
        L2 = __logf(T2 * (1.0f / 300.0f)); iT2 = 1.0f / T2;
        cr1 = cr[m0 + lane];  cr2 = cr[m0 + lane + 32];
        fv1 = fuv[m0 + lane]; fv2 = fuv[m0 + lane + 32];
    }

    // ---------------- Producer load lambdas (128 producer threads) ----------------
    const int ptid = tid - 128;  // 0..127 for producers
    auto load_B = [&](int kc) {
        const uint32_t base = sb + OFF_B + (kc % 3) * B_STAGE;
        const size_t k0 = (size_t)kc * TK;
#pragma unroll
        for (int q = 0; q < 16; q++) {
            int idx = q * 128 + ptid;          // 2048 16B-chunks total
            int row = idx >> 3, j = idx & 7;
            cp_async16(base + swz128((uint32_t)(row * 128 + j * 16)),
                       g_incT + (size_t)row * R + k0 + j * 4);
        }
    };
    auto load_P = [&](int kc) {
        const uint32_t pb = sb + OFF_P + (kc & 3) * P_STAGE;
        const int r0 = kc * TK;
        if (ptid < 8)       cp_async16(pb + ptid * 16, alpha + r0 + ptid * 4);
        else if (ptid < 16) cp_async16(pb + 128 + (ptid - 8) * 16, beta + r0 + (ptid - 8) * 4);
        else if (ptid < 24) cp_async16(pb + 256 + (ptid - 16) * 16, gamma + r0 + (ptid - 16) * 4);
        else if (ptid < 32) cp_async16(pb + 384 + (ptid - 24) * 16, rtype + r0 + (ptid - 24) * 4);
        else if (ptid < 48) cp_async16(pb + 512 + (ptid - 32) * 16, rm2 + 2 * r0 + (ptid - 32) * 4);
    };

    // Producer warp pw computes r_local = 8*pw .. 8*pw+7 for all 64 b's.
    // rtype branch warp-uniform; s_ab gather conflict-free (pitch 257).
    auto flux_compute = [&](int kc) {
        const char* pb = smem + OFF_P + (kc & 3) * P_STAGE;
        const float* pA  = reinterpret_cast<const float*>(pb);
        const float* pBe = reinterpret_cast<const float*>(pb + 128);
        const float* pGa = reinterpret_cast<const float*>(pb + 256);
        const int*   pRt = reinterpret_cast<const int*>(pb + 384);
        const int2*  pRm = reinterpret_cast<const int2*>(pb + 512);
        const uint32_t an = sb + OFF_A + (kc & 1) * A_STAGE;
        const int b1 = lane, b2 = lane + 32;
        uint32_t v1[8], v2[8];
#pragma unroll
        for (int i = 0; i < 8; i++) {
            const int rl = pw * 8 + i;
            const float a_ = pA[rl], be = pBe[rl], ga = pGa[rl];
            const int rt = pRt[rl];
            const int2 ii = pRm[rl];
            float k1, k2;
            if (rt == 0) {
                k1 = a_ * __expf(be * L1 - ga * iT1);
                k2 = a_ * __expf(be * L2 - ga * iT2);
            } else if (rt == 1) {
                k1 = a_ * cr1;
                k2 = a_ * cr2;
            } else {
                const float e = a_ * __expf(-ga);
                k1 = e * fv1;
                k2 = e * fv2;
            }
            v1[i] = f2tf32(k1 * s_ab[b1 * AB_PITCH + ii.x] * s_ab[b1 * AB_PITCH + ii.y]);
            v2[i] = f2tf32(k2 * s_ab[b2 * AB_PITCH + ii.x] * s_ab[b2 * AB_PITCH + ii.y]);
        }
#pragma unroll
        for (int q = 0; q < 2; q++) {
            const uint32_t col = (uint32_t)(pw * 32 + q * 16);
            sts128(an + swz128((uint32_t)(b1 * 128) + col),
                   v1[4 * q], v1[4 * q + 1], v1[4 * q + 2], v1[4 * q + 3]);
            sts128(an + swz128((uint32_t)(b2 * 128) + col),
                   v2[4 * q], v2[4 * q + 1], v2[4 * q + 2], v2[4 * q + 3]);
        }
    };

    // ---------------- ldmatrix per-lane address constants ----------------
    const int ldsmRowA = ((lane >> 3) & 1) * 8 + (lane & 7);
    const int ldsmColA = (lane >> 4) * 16;
    const int ldsmRowB = (lane >> 4) * 8 + (lane & 7);
    const int ldsmColB = ((lane >> 3) & 1) * 16;
    const int lr = lane >> 2;
    const int lc = lane & 3;

    float c[4][8][4];
#pragma unroll
    for (int g = 0; g < 4; g++)
#pragma unroll
        for (int j = 0; j < 8; j++)
#pragma unroll
            for (int q = 0; q < 4; q++) c[g][j][q] = 0.0f;

    // ---------------- Prologue pipeline ----------------
    if (is_prod) {
        load_B(0); load_P(0); load_P(1); cp_commit();   // G0
        load_B(1); load_P(2); cp_commit();              // G1
        cp_wait1();                                     // G0 done: B0,P0,P1
    }
    __syncthreads();           // s_ab + B0/P0/P1 visible to all
    if (is_prod) flux_compute(0);
    __syncthreads();           // A(0) visible

    // ---------------- Main loop ----------------
    for (int k = 0; k < NK; k++) {
        if (!is_prod) {
            // ---- Consumer: MMA(k), warp tile 64x64 ----
            const uint32_t abase = sb + OFF_A + (k & 1) * A_STAGE;
            const uint32_t bbase = sb + OFF_B + (k % 3) * B_STAGE;
#pragma unroll
            for (int ks = 0; ks < 4; ks++) {
                uint32_t a4[4][4];
#pragma unroll
                for (int g = 0; g < 4; g++)
                    ldsm_x4(a4[g], abase + swz128((uint32_t)(
                        (g * 16 + ldsmRowA) * 128 + ks * 32 + ldsmColA)));
                uint32_t bfr[4][4];
#pragma unroll
                for (int jj = 0; jj < 4; jj++)
                    ldsm_x4(bfr[jj], bbase + swz128((uint32_t)(
                        (warp_n * 64 + jj * 16 + ldsmRowB) * 128 + ks * 32 + ldsmColB)));
#pragma unroll
                for (int g = 0; g < 4; g++)
#pragma unroll
                    for (int jj = 0; jj < 4; jj++) {
                        mma_m16n8k8(c[g][2 * jj], a4[g], &bfr[jj][0]);
                        mma_m16n8k8(c[g][2 * jj + 1], a4[g], &bfr[jj][2]);
                    }
            }
        } else {
            // ---- Producer: loads + flux(k+1) + drain ----
            if (k + 2 < NK) load_B(k + 2);
            if (k + 3 < NK) load_P(k + 3);
            cp_commit();                    // G(k+2)
            if (k + 1 < NK) flux_compute(k + 1);
            cp_wait1();                     // G(k+1) done => B(k+1),P(k+2)
        }
        __syncthreads();
    }

    // ---------------- Epilogue (consumers only) ----------------
    if (!is_prod) {
#pragma unroll
        for (int g = 0; g < 4; g++) {
#pragma unroll
            for (int j = 0; j < 8; j++) {
                const int row = m0 + g * 16 + lr;
                const int col = warp_n * 64 + j * 8 + 2 * lc;
                float2 v0; v0.x = c[g][j][0]; v0.y = c[g][j][1];
                float2 v1; v1.x = c[g][j][2]; v1.y = c[g][j][3];
                *reinterpret_cast<float2*>(out + (size_t)row * S + col) = v0;
                *reinterpret_cast<float2*>(out + (size_t)(row + 8) * S + col) = v1;
            }
        }
    }
}

// =====================================================================
// Launch
// =====================================================================
extern "C" void kernel_launch(void* const* d_in, const int* in_sizes, int n_in,
                              void* d_out, int out_size) {
    // metadata order: time, abundances, temperature, cr_rate, fuv_rate,
    //                 incidence, alpha, beta, gamma, reactant_multipliers, rtype
    const float* ab    = (const float*)d_in[1];
    const float* temp  = (const float*)d_in[2];
    const float* cr    = (const float*)d_in[3];
    const float* fuv   = (const float*)d_in[4];
    const float* inc   = (const float*)d_in[5];
    const float* alpha = (const float*)d_in[6];
    const float* beta  = (const float*)d_in[7];
    const float* gamma = (const float*)d_in[8];
    const int*   rm    = (const int*)d_in[9];
    const int*   rtype = (const int*)d_in[10];
    float* out = (float*)d_out;

    cudaFuncSetAttribute(fused_kernel,
                         cudaFuncAttributeMaxDynamicSharedMemorySize, SMEM_TOTAL);

    conv_inc_kernel<<<(S * R) / (256 * 4), 256>>>(inc);
    fused_kernel<<<B / TM, 256, SMEM_TOTAL>>>(ab, temp, cr, fuv, alpha, beta,
                                              gamma, rm, rtype, out);
}

// round 15
// speedup vs baseline: 1.6308x; 1.6308x over previous
#include <cuda_runtime.h>
#include <cstdint>
#include <cstddef>

// Problem constants
static constexpr int B = 8192;
static constexpr int S = 256;
static constexpr int R = 8192;

// 8 MB scratch: inc pre-converted to tf32 bit patterns (device global = sanctioned scratch)
__device__ uint32_t g_incT[(size_t)S * (size_t)R];

// =====================================================================
// Helpers (sm_80-baseline PTX only)
// =====================================================================
__device__ __forceinline__ uint32_t smem_u32(const void* p) {
    uint32_t a;
    asm("{ .reg .u64 t; cvta.to.shared.u64 t, %1; cvt.u32.u64 %0, t; }"
        : "=r"(a) : "l"(p));
    return a;
}
__device__ __forceinline__ void cp_async16(uint32_t s, const void* g) {
    asm volatile("cp.async.cg.shared.global [%0], [%1], 16;"
                 :: "r"(s), "l"(g) : "memory");
}
__device__ __forceinline__ void cp_commit() {
    asm volatile("cp.async.commit_group;" ::: "memory");
}
__device__ __forceinline__ void cp_wait1() {
    asm volatile("cp.async.wait_group 1;" ::: "memory");
}
// SW128 swizzle: XOR byte-addr bits [6:4] with bits [9:7]
__device__ __forceinline__ uint32_t swz128(uint32_t off) {
    return off ^ ((off >> 3) & 0x70);
}
__device__ __forceinline__ uint32_t f2tf32(float f) {
    uint32_t t;
    asm("cvt.rna.tf32.f32 %0, %1;" : "=r"(t) : "f"(f));
    return t;
}
__device__ __forceinline__ void ldsm_x4(uint32_t* r, uint32_t addr) {
    asm volatile("ldmatrix.sync.aligned.m8n8.x4.shared.b16 {%0,%1,%2,%3}, [%4];"
                 : "=r"(r[0]), "=r"(r[1]), "=r"(r[2]), "=r"(r[3]) : "r"(addr));
}
__device__ __forceinline__ void sts64(uint32_t addr, uint32_t v0, uint32_t v1) {
    asm volatile("st.shared.v2.b32 [%0], {%1,%2};"
                 :: "r"(addr), "r"(v0), "r"(v1) : "memory");
}
__device__ __forceinline__ void mma_m16n8k8(float* c, const uint32_t* a,
                                            const uint32_t* b) {
    asm volatile(
        "mma.sync.aligned.m16n8k8.row.col.f32.tf32.tf32.f32 "
        "{%0,%1,%2,%3}, {%4,%5,%6,%7}, {%8,%9}, {%0,%1,%2,%3};"
        : "+f"(c[0]), "+f"(c[1]), "+f"(c[2]), "+f"(c[3])
        : "r"(a[0]), "r"(a[1]), "r"(a[2]), "r"(a[3]),
          "r"(b[0]), "r"(b[1]));
}

// =====================================================================
// inc -> tf32-bits pre-convert (one-shot, ~5us)
// =====================================================================
__global__ void __launch_bounds__(256) conv_inc_kernel(const float* __restrict__ inc) {
    size_t i = ((size_t)blockIdx.x * 256 + threadIdx.x) * 4;
    float4 v = *reinterpret_cast<const float4*>(inc + i);
    uint4 o;
    o.x = f2tf32(v.x); o.y = f2tf32(v.y); o.z = f2tf32(v.z); o.w = f2tf32(v.w);
    *reinterpret_cast<uint4*>(g_incT + i) = o;
}

// =====================================================================
// Fused flux + GEMM, unified loop (R4 dataflow, proven 353us) at
// 512 THREADS / 16 WARPS: 4 warps per SMSP for latency hiding.
// Warp tile 32x32 (warp_m = wid&1 over M, warp_n = wid>>1 over N).
// CTA tile M=64 x N=256 x TK=32, one __syncthreads per K-chunk.
// Groups committed in iter k (after barrier): G(k+2)={B(k+2),P(k+3)}.
// wait_group 1 at iter k => B(k),P(k+1) resident. Rings A x2, B x3, P x4.
// =====================================================================
static constexpr int THREADS = 512;
static constexpr int TM = 64, TN = 256, TK = 32;
static constexpr int NK = R / TK;  // 256

static constexpr int A_STAGE = TM * TK * 4;          // 8192
static constexpr int B_STAGE = TN * TK * 4;          // 32768
static constexpr int P_STAGE = 768;
static constexpr int OFF_A = 0;
static constexpr int OFF_B = OFF_A + 2 * A_STAGE;    // 16384
static constexpr int OFF_P = OFF_B + 3 * B_STAGE;    // 114688
static constexpr int OFF_AB = OFF_P + 4 * P_STAGE;   // 117760
static constexpr int AB_PITCH = S + 1;               // 257 (odd: conflict-free gather)
static constexpr int SMEM_USED = OFF_AB + TM * AB_PITCH * 4;  // 183552
static constexpr int SMEM_TOTAL = SMEM_USED + 1024;  // alignment slack

__global__ void __launch_bounds__(THREADS, 1) fused_kernel(
    const float* __restrict__ ab, const float* __restrict__ temp,
    const float* __restrict__ cr, const float* __restrict__ fuv,
    const float* __restrict__ alpha, const float* __restrict__ beta,
    const float* __restrict__ gamma, const int* __restrict__ rm2,
    const int* __restrict__ rtype, float* __restrict__ out)
{
    extern __shared__ char smem_raw[];
    const uint32_t sb_raw = smem_u32(smem_raw);
    const uint32_t sb = (sb_raw + 1023u) & ~1023u;   // SW128-safe tile bases
    char* smem = smem_raw + (sb - sb_raw);

    const int tid = threadIdx.x;
    const int wid = tid >> 5;          // 0..15
    const int lane = tid & 31;
    const int m0 = blockIdx.x * TM;
    const int warp_m = wid & 1;        // 2 over M (32 rows each)
    const int warp_n = wid >> 1;       // 8 over N (32 cols each)

    float* s_ab = reinterpret_cast<float*>(smem + OFF_AB);

    // ---------------- Prologue: abundances + per-lane aux regs ----------------
    for (int i = tid; i < TM * S; i += THREADS) {
        int bi = i >> 8, si = i & 255;
        s_ab[bi * AB_PITCH + si] = ab[(size_t)(m0 + bi) * S + si];
    }
    if (tid < TM) s_ab[tid * AB_PITCH + S] = 1.0f;  // ones column (index == S)

    // Every thread: aux for its two b's (b1 = lane, b2 = lane+32); L1-broadcast
    const float T1 = temp[m0 + lane], T2 = temp[m0 + lane + 32];
    const float L1 = __logf(T1 * (1.0f / 300.0f)), iT1 = 1.0f / T1;
    const float L2 = __logf(T2 * (1.0f / 300.0f)), iT2 = 1.0f / T2;
    const float cr1 = cr[m0 + lane],  cr2 = cr[m0 + lane + 32];
    const float fv1 = fuv[m0 + lane], fv2 = fuv[m0 + lane + 32];

    // ---------------- Load lambdas (all 512 threads) ----------------
    auto load_B = [&](int kc) {
        const uint32_t base = sb + OFF_B + (kc % 3) * B_STAGE;
        const size_t k0 = (size_t)kc * TK;
#pragma unroll
        for (int q = 0; q < 4; q++) {
            int idx = q * THREADS + tid;       // 2048 16B-chunks total
            int row = idx >> 3, j = idx & 7;
            cp_async16(base + swz128((uint32_t)(row * 128 + j * 16)),
                       g_incT + (size_t)row * R + k0 + j * 4);
        }
    };
    auto load_P = [&](int kc) {
        const uint32_t pb = sb + OFF_P + (kc & 3) * P_STAGE;
        const int r0 = kc * TK;
        if (tid < 8)       cp_async16(pb + tid * 16, alpha + r0 + tid * 4);
        else if (tid < 16) cp_async16(pb + 128 + (tid - 8) * 16, beta + r0 + (tid - 8) * 4);
        else if (tid < 24) cp_async16(pb + 256 + (tid - 16) * 16, gamma + r0 + (tid - 16) * 4);
        else if (tid < 32) cp_async16(pb + 384 + (tid - 24) * 16, rtype + r0 + (tid - 24) * 4);
        else if (tid < 48) cp_async16(pb + 512 + (tid - 32) * 16, rm2 + 2 * r0 + (tid - 32) * 4);
    };

    // Flux: warp w computes r_local = 2w, 2w+1 for all 64 b's.
    // rtype warp-uniform; s_ab gather conflict-free (pitch 257, uniform index).
    auto flux_compute = [&](int kc) {
        const char* pb = smem + OFF_P + (kc & 3) * P_STAGE;
        const float* pA  = reinterpret_cast<const float*>(pb);
        const float* pBe = reinterpret_cast<const float*>(pb + 128);
        const float* pGa = reinterpret_cast<const float*>(pb + 256);
        const int*   pRt = reinterpret_cast<const int*>(pb + 384);
        const int2*  pRm = reinterpret_cast<const int2*>(pb + 512);
        const uint32_t an = sb + OFF_A + (kc & 1) * A_STAGE;
        const int b1 = lane, b2 = lane + 32;
        uint32_t v1[2], v2[2];
#pragma unroll
        for (int i = 0; i < 2; i++) {
            const int rl = wid * 2 + i;
            const float a_ = pA[rl], be = pBe[rl], ga = pGa[rl];
            const int rt = pRt[rl];
            const int2 ii = pRm[rl];
            float k1, k2;
            if (rt == 0) {
                k1 = a_ * __expf(be * L1 - ga * iT1);
                k2 = a_ * __expf(be * L2 - ga * iT2);
            } else if (rt == 1) {
                k1 = a_ * cr1;
                k2 = a_ * cr2;
            } else {
                const float e = a_ * __expf(-ga);
                k1 = e * fv1;
                k2 = e * fv2;
            }
            v1[i] = f2tf32(k1 * s_ab[b1 * AB_PITCH + ii.x] * s_ab[b1 * AB_PITCH + ii.y]);
            v2[i] = f2tf32(k2 * s_ab[b2 * AB_PITCH + ii.x] * s_ab[b2 * AB_PITCH + ii.y]);
        }
        sts64(an + swz128((uint32_t)(b1 * 128 + wid * 8)), v1[0], v1[1]);
        sts64(an + swz128((uint32_t)(b2 * 128 + wid * 8)), v2[0], v2[1]);
    };

    // ---------------- ldmatrix per-lane address constants ----------------
    const int ldsmRowA = ((lane >> 3) & 1) * 8 + (lane & 7);
    const int ldsmColA = (lane >> 4) * 16;
    const int ldsmRowB = (lane >> 4) * 8 + (lane & 7);
    const int ldsmColB = ((lane >> 3) & 1) * 16;
    const int lr = lane >> 2;
    const int lc = lane & 3;

    float c[2][4][4];
#pragma unroll
    for (int g = 0; g < 2; g++)
#pragma unroll
        for (int j = 0; j < 4; j++)
#pragma unroll
            for (int q = 0; q < 4; q++) c[g][j][q] = 0.0f;

    // ---------------- Prologue pipeline ----------------
    // G0 = {B0, P0, P1}; G1 = {B1, P2}
    load_B(0); load_P(0); load_P(1); cp_commit();
    load_B(1); load_P(2); cp_commit();
    cp_wait1();        // G0 done: B0, P0, P1 ready
    __syncthreads();   // s_ab visible
    flux_compute(0);   // A(0) -> abuf[0]  (needs P0)

    // ---------------- Main loop ----------------
    for (int k = 0; k < NK; k++) {
        cp_wait1();        // group k done => B(k), P(k+1) ready
        __syncthreads();   // A(k)+B(k) visible; all readers of buf (k+2)%3 done

        if (k + 2 < NK) load_B(k + 2);
        if (k + 3 < NK) load_P(k + 3);
        cp_commit();       // G(k+2)

        // ---- MMA(k): warp tile 32x32 ----
        const uint32_t abase = sb + OFF_A + (k & 1) * A_STAGE;
        const uint32_t bbase = sb + OFF_B + (k % 3) * B_STAGE;
#pragma unroll
        for (int ks = 0; ks < 4; ks++) {
            uint32_t a2[2][4];
#pragma unroll
            for (int g = 0; g < 2; g++)
                ldsm_x4(a2[g], abase + swz128((uint32_t)(
                    (warp_m * 32 + g * 16 + ldsmRowA) * 128 + ks * 32 + ldsmColA)));
            uint32_t bfr[2][4];
#pragma unroll
            for (int jj = 0; jj < 2; jj++)
                ldsm_x4(bfr[jj], bbase + swz128((uint32_t)(
                    (warp_n * 32 + jj * 16 + ldsmRowB) * 128 + ks * 32 + ldsmColB)));
#pragma unroll
            for (int g = 0; g < 2; g++)
#pragma unroll
                for (int jj = 0; jj < 2; jj++) {
                    mma_m16n8k8(c[g][2 * jj], a2[g], &bfr[jj][0]);
                    mma_m16n8k8(c[g][2 * jj + 1], a2[g], &bfr[jj][2]);
                }
        }

        // ---- Produce A(k+1) into the other A buffer (needs P(k+1): ready) ----
        if (k + 1 < NK) flux_compute(k + 1);
    }

    // ---------------- Epilogue ----------------
#pragma unroll
    for (int g = 0; g < 2; g++) {
#pragma unroll
        for (int j = 0; j < 4; j++) {
            const int row = m0 + warp_m * 32 + g * 16 + lr;
            const int col = warp_n * 32 + j * 8 + 2 * lc;
            float2 v0; v0.x = c[g][j][0]; v0.y = c[g][j][1];
            float2 v1; v1.x = c[g][j][2]; v1.y = c[g][j][3];
            *reinterpret_cast<float2*>(out + (size_t)row * S + col) = v0;
            *reinterpret_cast<float2*>(out + (size_t)(row + 8) * S + col) = v1;
        }
    }
}

// =====================================================================
// Launch
// =====================================================================
extern "C" void kernel_launch(void* const* d_in, const int* in_sizes, int n_in,
                              void* d_out, int out_size) {
    // metadata order: time, abundances, temperature, cr_rate, fuv_rate,
    //                 incidence, alpha, beta, gamma, reactant_multipliers, rtype
    const float* ab    = (const float*)d_in[1];
    const float* temp  = (const float*)d_in[2];
    const float* cr    = (const float*)d_in[3];
    const float* fuv   = (const float*)d_in[4];
    const float* inc   = (const float*)d_in[5];
    const float* alpha = (const float*)d_in[6];
    const float* beta  = (const float*)d_in[7];
    const float* gamma = (const float*)d_in[8];
    const int*   rm    = (const int*)d_in[9];
    const int*   rtype = (const int*)d_in[10];
    float* out = (float*)d_out;

    cudaFuncSetAttribute(fused_kernel,
                         cudaFuncAttributeMaxDynamicSharedMemorySize, SMEM_TOTAL);

    conv_inc_kernel<<<(S * R) / (256 * 4), 256>>>(inc);
    fused_kernel<<<B / TM, THREADS, SMEM_TOTAL>>>(ab, temp, cr, fuv, alpha, beta,
                                                  gamma, rm, rtype, out);
}